// round 2
// baseline (speedup 1.0000x reference)
#include <cuda_runtime.h>

// ROIAlignRotated3D for fixed shapes:
//   input: (B=2, C=128, W=64, L=64, H=64) f32, rois: (N=128, 8) f32, scalar spatial_scale
//   output: (N, C, 7, 7, 7) f32
//
// One block per (roi n, channel pair). 343 worker threads = one output bin each,
// each thread accumulates 2 channels (doubles MLP, amortizes the per-block
// shared sample-table precompute over 2x the gather work).
//
// Separable precompute in shared memory:
//   xy: 14x14 rotated (x,y) -> base offset, dx, dy, lx, ly, valid_xy
//   z : 14 z samples        -> z0, dz, lz, valid_z

#define OW      7
#define NS      14          // OW * SR
#define BINS    343         // 7*7*7
#define CH      128
#define CPB     2           // channels per block
#define WD      64
#define LDIM    64
#define HDIM    64
#define VOLSZ   (WD * LDIM * HDIM)
#define NTHREADS 352        // 11 warps; threads >= 343 idle in main loop

__global__ __launch_bounds__(NTHREADS)
void roi_align_rot3d_kernel(const float* __restrict__ input,
                            const float* __restrict__ rois,
                            const float* __restrict__ ssp,
                            float* __restrict__ out)
{
    __shared__ int   s_base[NS * NS];
    __shared__ int   s_dx  [NS * NS];
    __shared__ int   s_dy  [NS * NS];
    __shared__ float s_lx  [NS * NS];
    __shared__ float s_ly  [NS * NS];
    __shared__ float s_vxy [NS * NS];
    __shared__ int   s_z0  [NS];
    __shared__ int   s_dz  [NS];
    __shared__ float s_lz  [NS];
    __shared__ float s_vz  [NS];
    __shared__ float s_roi [8];

    const int n   = blockIdx.x;        // roi index (fast-varying -> cross-block L2 reuse)
    const int c0  = blockIdx.y * CPB;  // first channel of the pair
    const int tid = threadIdx.x;

    if (tid < 8) s_roi[tid] = rois[n * 8 + tid];
    __syncthreads();

    const float ss = __ldg(ssp);
    const int   b  = (int)s_roi[0];
    const float cx = s_roi[1] * ss, cy = s_roi[2] * ss, cz = s_roi[3] * ss;
    const float sx = s_roi[4] * ss, sy = s_roi[5] * ss, sz = s_roi[6] * ss;
    const float th = s_roi[7];

    // -------- per-block sample-table precompute (separable x/y vs z) --------
    if (tid < NS * NS) {
        float ct, st;
        sincosf(th, &st, &ct);
        const int i = tid / NS;   // x sample index
        const int j = tid % NS;   // y sample index
        const float ox = -0.5f * sx + ((float)i + 0.5f) * (sx * (1.0f / NS));
        const float oy = -0.5f * sy + ((float)j + 0.5f) * (sy * (1.0f / NS));
        float x = ct * ox - st * oy + cx;
        float y = st * ox + ct * oy + cy;
        const float v = (x > -1.0f && x < (float)WD && y > -1.0f && y < (float)LDIM) ? 1.0f : 0.0f;
        x = fminf(fmaxf(x, 0.0f), (float)(WD - 1));
        y = fminf(fmaxf(y, 0.0f), (float)(LDIM - 1));
        const int x0 = (int)floorf(x);
        const int y0 = (int)floorf(y);
        const int x1 = min(x0 + 1, WD - 1);
        const int y1 = min(y0 + 1, LDIM - 1);
        s_base[tid] = x0 * (LDIM * HDIM) + y0 * HDIM;
        s_dx  [tid] = (x1 - x0) * (LDIM * HDIM);
        s_dy  [tid] = (y1 - y0) * HDIM;
        s_lx  [tid] = x - (float)x0;
        s_ly  [tid] = y - (float)y0;
        s_vxy [tid] = v;
    } else if (tid < NS * NS + NS) {
        const int l = tid - NS * NS;  // z sample index
        const float oz = -0.5f * sz + ((float)l + 0.5f) * (sz * (1.0f / NS));
        float z = oz + cz;
        const float v = (z > -1.0f && z < (float)HDIM) ? 1.0f : 0.0f;
        z = fminf(fmaxf(z, 0.0f), (float)(HDIM - 1));
        const int z0 = (int)floorf(z);
        const int z1 = min(z0 + 1, HDIM - 1);
        s_z0[l] = z0;
        s_dz[l] = z1 - z0;
        s_lz[l] = z - (float)z0;
        s_vz[l] = v;
    }
    __syncthreads();

    if (tid >= BINS) return;

    const int ix  = tid / 49;
    const int rem = tid - ix * 49;
    const int iy  = rem / 7;
    const int iz  = rem - iy * 7;

    const float* __restrict__ vol0 =
        input + ((size_t)b * CH + (size_t)c0) * (size_t)VOLSZ;
    const float* __restrict__ vol1 = vol0 + VOLSZ;

    float acc0 = 0.0f;
    float acc1 = 0.0f;

    #pragma unroll
    for (int j = 0; j < 2; j++) {
        #pragma unroll
        for (int k = 0; k < 2; k++) {
            const int   p    = (ix * 2 + j) * NS + (iy * 2 + k);
            const int   base = s_base[p];
            const int   dx   = s_dx[p];
            const int   dy   = s_dy[p];
            const float lx   = s_lx[p];
            const float ly   = s_ly[p];
            const float vxy  = s_vxy[p];
            #pragma unroll
            for (int l = 0; l < 2; l++) {
                const int   zi  = iz * 2 + l;
                const int   idx = base + s_z0[zi];
                const int   dz  = s_dz[zi];
                const float lz  = s_lz[zi];
                const float v   = vxy * s_vz[zi];

                const int i000 = idx;
                const int i001 = idx + dz;
                const int i010 = idx + dy;
                const int i011 = idx + dy + dz;
                const int i100 = idx + dx;
                const int i101 = idx + dx + dz;
                const int i110 = idx + dx + dy;
                const int i111 = idx + dx + dy + dz;

                // channel 0 and channel 1 gathers interleaved -> 16 independent
                // outstanding loads per sample (MLP)
                const float a000 = vol0[i000];
                const float b000 = vol1[i000];
                const float a001 = vol0[i001];
                const float b001 = vol1[i001];
                const float a010 = vol0[i010];
                const float b010 = vol1[i010];
                const float a011 = vol0[i011];
                const float b011 = vol1[i011];
                const float a100 = vol0[i100];
                const float b100 = vol1[i100];
                const float a101 = vol0[i101];
                const float b101 = vol1[i101];
                const float a110 = vol0[i110];
                const float b110 = vol1[i110];
                const float a111 = vol0[i111];
                const float b111 = vol1[i111];

                {
                    const float t00 = a000 + lx * (a100 - a000);
                    const float t01 = a001 + lx * (a101 - a001);
                    const float t10 = a010 + lx * (a110 - a010);
                    const float t11 = a011 + lx * (a111 - a011);
                    const float u0  = t00 + ly * (t10 - t00);
                    const float u1  = t01 + ly * (t11 - t01);
                    const float sv  = u0 + lz * (u1 - u0);
                    acc0 = fmaf(v, sv, acc0);
                }
                {
                    const float t00 = b000 + lx * (b100 - b000);
                    const float t01 = b001 + lx * (b101 - b001);
                    const float t10 = b010 + lx * (b110 - b010);
                    const float t11 = b011 + lx * (b111 - b011);
                    const float u0  = t00 + ly * (t10 - t00);
                    const float u1  = t01 + ly * (t11 - t01);
                    const float sv  = u0 + lz * (u1 - u0);
                    acc1 = fmaf(v, sv, acc1);
                }
            }
        }
    }

    float* obase = out + ((size_t)n * CH + (size_t)c0) * BINS + (size_t)tid;
    obase[0]    = acc0 * 0.125f;
    obase[BINS] = acc1 * 0.125f;
}

extern "C" void kernel_launch(void* const* d_in, const int* in_sizes, int n_in,
                              void* d_out, int out_size)
{
    const float* input = (const float*)d_in[0];
    const float* rois  = (const float*)d_in[1];
    const float* ss    = (const float*)d_in[2];
    float* out         = (float*)d_out;

    const int N = in_sizes[1] / 8;   // rois rows

    dim3 grid(N, CH / CPB, 1);
    roi_align_rot3d_kernel<<<grid, NTHREADS>>>(input, rois, ss, out);
}